// round 10
// baseline (speedup 1.0000x reference)
#include <cuda_runtime.h>
#include <cuda_bf16.h>

// EEBasis: out[n, 0, s] = exp(-|zeta[s]| * sqrt(diffs[n, center_idxs[s], 3]))
// N = 262144 rows, 64 centers (float4: dx,dy,dz,r2), 256 shells (4/center).
//
// R2 structure (measured fastest across R1-R9 sweep) with one change:
// load ONLY diffs[...].w as a scalar LDG.32 (byte offset +12), threads
// 16 B apart -> same 4 cache lines per warp as the LDG.128 (same DRAM
// sectors, traffic floor unchanged) but 4x less L1->RF return bandwidth
// and lower register pressure.
//  - __ldcs loads (evict-first), __stcs stores (streaming)
//  - 2 items per thread, split total/2 apart, loads front-batched (MLP=2)
// Sweep evidence: MLP=4 overflows the L1tex queue (R3); persistent loops
// serialize the stream (R4); intra-thread-adjacent pairs double L1
// wavefronts (R5); block-local windows / 512-thr CTAs neutral (R6, R7).

__global__ void __launch_bounds__(256) eebasis_kernel(
    const float*  __restrict__ diffs,       // [N*64*4] f32 (use .w = +3)
    const float4* __restrict__ zetas4,      // [64] float4 (256 zetas)
    const int*    __restrict__ center_idxs, // [256]
    float4*       __restrict__ out,         // [N*64] float4
    int half)                                // total/2
{
    int i0 = blockIdx.x * blockDim.x + threadIdx.x;
    if (i0 >= half) return;
    int i1 = i0 + half;

    int g0 = i0 & 63, n0 = i0 >> 6;
    int g1 = i1 & 63, n1 = i1 >> 6;

    // gather table (1KB, L1-resident)
    int c0 = __ldg(&center_idxs[4 * g0]);
    int c1 = __ldg(&center_idxs[4 * g1]);

    // front-batched scalar streaming loads of r^2 only (MLP = 2);
    // 16B thread stride -> 4 lines/warp, identical DRAM sectors to LDG.128
    float w0 = __ldcs(&diffs[(n0 * 64 + c0) * 4 + 3]);
    float w1 = __ldcs(&diffs[(n1 * 64 + c1) * 4 + 3]);

    float4 z0 = __ldg(&zetas4[g0]);   // 1KB table, L1-resident
    float4 z1 = __ldg(&zetas4[g1]);

    float r0 = sqrtf(w0);
    float r1 = sqrtf(w1);

    float4 o0, o1;
    o0.x = __expf(-fabsf(z0.x) * r0);
    o0.y = __expf(-fabsf(z0.y) * r0);
    o0.z = __expf(-fabsf(z0.z) * r0);
    o0.w = __expf(-fabsf(z0.w) * r0);

    o1.x = __expf(-fabsf(z1.x) * r1);
    o1.y = __expf(-fabsf(z1.y) * r1);
    o1.z = __expf(-fabsf(z1.z) * r1);
    o1.w = __expf(-fabsf(z1.w) * r1);

    __stcs(&out[i0], o0);
    __stcs(&out[i1], o1);
}

extern "C" void kernel_launch(void* const* d_in, const int* in_sizes, int n_in,
                              void* d_out, int out_size)
{
    const float* diffs       = (const float*)d_in[0];  // [N, 64, 4] f32
    const float* zetas       = (const float*)d_in[1];  // [256] f32
    const int*   center_idxs = (const int*)  d_in[2];  // [256] i32

    int n_rows = in_sizes[0] / (64 * 4);
    int total  = n_rows * 64;
    int half   = total / 2;   // N is a power of two; total even

    int threads = 256;
    int blocks  = (half + threads - 1) / threads;

    eebasis_kernel<<<blocks, threads>>>(
        diffs,
        (const float4*)zetas,
        center_idxs,
        (float4*)d_out,
        half);
}

// round 11
// speedup vs baseline: 1.0147x; 1.0147x over previous
#include <cuda_runtime.h>
#include <cuda_bf16.h>
#include <cstdint>

// EEBasis: out[n, 0, s] = exp(-|zeta[s]| * sqrt(diffs[n, center_idxs[s], 3]))
// N = 262144 rows, 64 centers (float4: dx,dy,dz,r2), 256 shells (4/center).
//
// R2 structure (fastest across R1-R10 sweep: split-half MLP2, unit-stride
// streams, __ldcs/__stcs, 256-thread flat grid) + one new mechanism:
// loads carry the PTX L2::256B fetch-promotion hint, batching DRAM reads
// into larger row-hit bursts to cut read/write bus-turnaround losses
// (the residual vs the ~80%-of-spec mixed-stream plateau). Traffic
// unchanged — this is a pure stream, all promoted bytes are consumed.
//
// Sweep evidence: MLP=4 overflows the L1tex queue (R3); persistent loops
// serialize the stream (R4); intra-thread-adjacent pairs double L1
// wavefronts (R5); block-local windows / 512-thr CTAs neutral (R6, R7);
// scalar .w loads neutral — L1 counts sectors, not bytes (R10).

__device__ __forceinline__ float4 ldcs_256B(const float4* p) {
    float4 v;
    asm volatile("ld.global.cs.L2::256B.v4.f32 {%0,%1,%2,%3}, [%4];"
                 : "=f"(v.x), "=f"(v.y), "=f"(v.z), "=f"(v.w)
                 : "l"(p));
    return v;
}

__global__ void __launch_bounds__(256) eebasis_kernel(
    const float4* __restrict__ diffs,       // [N*64] float4
    const float4* __restrict__ zetas4,      // [64] float4 (256 zetas)
    const int*    __restrict__ center_idxs, // [256]
    float4*       __restrict__ out,         // [N*64] float4
    int half)                                // total/2
{
    int i0 = blockIdx.x * blockDim.x + threadIdx.x;
    if (i0 >= half) return;
    int i1 = i0 + half;

    int g0 = i0 & 63, n0 = i0 >> 6;
    int g1 = i1 & 63, n1 = i1 >> 6;

    // gather table (1KB, L1-resident)
    int c0 = __ldg(&center_idxs[4 * g0]);
    int c1 = __ldg(&center_idxs[4 * g1]);

    // front-batched streaming loads (MLP = 2), unit-stride across warp,
    // with 256B L2 fetch promotion for DRAM row-hit batching
    float4 d0 = ldcs_256B(&diffs[n0 * 64 + c0]);
    float4 d1 = ldcs_256B(&diffs[n1 * 64 + c1]);

    float4 z0 = __ldg(&zetas4[g0]);   // 1KB table, L1-resident
    float4 z1 = __ldg(&zetas4[g1]);

    float r0 = sqrtf(d0.w);
    float r1 = sqrtf(d1.w);

    float4 o0, o1;
    o0.x = __expf(-fabsf(z0.x) * r0);
    o0.y = __expf(-fabsf(z0.y) * r0);
    o0.z = __expf(-fabsf(z0.z) * r0);
    o0.w = __expf(-fabsf(z0.w) * r0);

    o1.x = __expf(-fabsf(z1.x) * r1);
    o1.y = __expf(-fabsf(z1.y) * r1);
    o1.z = __expf(-fabsf(z1.z) * r1);
    o1.w = __expf(-fabsf(z1.w) * r1);

    __stcs(&out[i0], o0);
    __stcs(&out[i1], o1);
}

extern "C" void kernel_launch(void* const* d_in, const int* in_sizes, int n_in,
                              void* d_out, int out_size)
{
    const float* diffs       = (const float*)d_in[0];  // [N, 64, 4] f32
    const float* zetas       = (const float*)d_in[1];  // [256] f32
    const int*   center_idxs = (const int*)  d_in[2];  // [256] i32

    int n_rows = in_sizes[0] / (64 * 4);
    int total  = n_rows * 64;
    int half   = total / 2;   // N is a power of two; total even

    int threads = 256;
    int blocks  = (half + threads - 1) / threads;

    eebasis_kernel<<<blocks, threads>>>(
        (const float4*)diffs,
        (const float4*)zetas,
        center_idxs,
        (float4*)d_out,
        half);
}